// round 1
// baseline (speedup 1.0000x reference)
#include <cuda_runtime.h>
#include <math.h>

#define BATCH 16
#define NHEAD 8
#define HDIM 128
#define BSZ 16
#define SEQL 4096
#define MAXB 384
#define HID 1024
#define NTOK 4097          // 4080 window + 16 partial block + 1 new token
#define NSPLIT 32
#define TPS 129            // ceil(4097/32)
#define KSPLIT 16
#define GEMM_KB 64         // 1024 / 16

// ---------------- scratch (device globals: no allocation allowed) ----------
__device__ float g_part_acc[BATCH * NSPLIT * NHEAD * HDIM]; // 2 MB
__device__ float g_part_m[BATCH * NSPLIT * NHEAD];
__device__ float g_part_l[BATCH * NSPLIT * NHEAD];
__device__ float g_attn[BATCH * HID];
__device__ float g_gemm_part[KSPLIT * BATCH * HID];         // 1 MB

__device__ __forceinline__ float4 ldg4(const float* p) {
    return *reinterpret_cast<const float4*>(p);
}

// ---------------------------------------------------------------------------
// Kernel A: split-token online-softmax attention partials.
// grid = (NSPLIT, BATCH), block = 256 (warp w == head w)
// ---------------------------------------------------------------------------
__global__ __launch_bounds__(256) void attn_partial_kernel(
    const float* __restrict__ q, const float* __restrict__ k,
    const float* __restrict__ v, const float* __restrict__ kc,
    const float* __restrict__ vc, const int* __restrict__ bt,
    const int* __restrict__ sl)
{
    __shared__ float invfS[64];
    __shared__ float cs[8][64];
    __shared__ float ss[8][64];

    const int b = blockIdx.y;
    const int s = blockIdx.x;
    const int tid = threadIdx.x;
    const int warp = tid >> 5;
    const int lane = tid & 31;
    const int h = warp;

    if (tid < 64)
        invfS[tid] = (float)(1.0 / pow(10000.0, (double)tid / 64.0));
    __syncthreads();

    const int seqlen = sl[b];
    const int num_past = seqlen - 1;
    const int mblk = num_past >> 4;
    const int rem = num_past & 15;
    const int* btb = bt + b * MAXB;

    // --- rope q at pos 4095, keep in registers ---
    const int fl = (lane & 15) * 4;
    const bool lo = lane < 16;
    float qc[4], qs[4];
#pragma unroll
    for (int j = 0; j < 4; j++) {
        float ang = 4095.0f * invfS[fl + j];
        sincosf(ang, &qs[j], &qc[j]);
    }
    float4 qv4 = ldg4(q + b * HID + h * HDIM + lane * 4);
    float qa[4] = {qv4.x, qv4.y, qv4.z, qv4.w};
    float qp[4], qr[4];
#pragma unroll
    for (int j = 0; j < 4; j++) qp[j] = __shfl_xor_sync(0xffffffffu, qa[j], 16);
#pragma unroll
    for (int j = 0; j < 4; j++)
        qr[j] = lo ? qa[j] * qc[j] - qp[j] * qs[j]
                   : qa[j] * qc[j] + qp[j] * qs[j];

    float mval = -INFINITY, lsum = 0.0f;
    float acc[4] = {0.f, 0.f, 0.f, 0.f};

    const int tstart = s * TPS;
    const int tend = min(tstart + TPS, NTOK);

    for (int t0 = tstart; t0 < tend; t0 += 8) {
        const int nt = min(8, tend - t0);
        __syncthreads();  // protect cs/ss from previous chunk readers
        // ---- cooperative sincos staging: 8 tokens x 64 freqs ----
#pragma unroll
        for (int e = tid; e < 512; e += 256) {
            int ti = e >> 6;
            if (ti < nt) {
                int t = t0 + ti;
                int p;
                if (t < 16)        p = t;
                else if (t < 4080) p = t + 15 - rem;
                else if (t < 4096) p = t - 1 - rem;
                else               p = 4095;
                int f = e & 63;
                float ang = (float)p * invfS[f];
                float sv, cv;
                sincosf(ang, &sv, &cv);
                cs[ti][f] = cv;
                ss[ti][f] = sv;
            }
        }
        __syncthreads();

#pragma unroll
        for (int i = 0; i < 8; i++) {
            const int t = t0 + i;
            if (t >= tend) break;
            bool isNew = (t == 4096);
            bool valid = true;
            long base = 0;
            if (t < 16) {
                int blk = btb[0];
                base = ((long)blk * BSZ + t) * (NHEAD * HDIM);
            } else if (t < 4080) {
                int jj = (t - 16) >> 4;
                int blk = btb[mblk - 254 + jj];
                base = ((long)blk * BSZ + ((t - 16) & 15)) * (NHEAD * HDIM);
            } else if (t < 4096) {
                int off = t - 4080;
                valid = off < rem;
                int blk = btb[mblk];
                base = ((long)blk * BSZ + off) * (NHEAD * HDIM);
            }
            if (!valid) continue;

            const float* kptr = isNew ? (k + b * HID + h * HDIM + lane * 4)
                                      : (kc + base + h * HDIM + lane * 4);
            const float* vptr = isNew ? (v + b * HID + h * HDIM + lane * 4)
                                      : (vc + base + h * HDIM + lane * 4);
            float4 kv4 = ldg4(kptr);
            float4 vv4 = ldg4(vptr);
            float ka[4] = {kv4.x, kv4.y, kv4.z, kv4.w};
            float va[4] = {vv4.x, vv4.y, vv4.z, vv4.w};
            float kp[4];
#pragma unroll
            for (int j = 0; j < 4; j++)
                kp[j] = __shfl_xor_sync(0xffffffffu, ka[j], 16);

            float dot = 0.0f;
#pragma unroll
            for (int j = 0; j < 4; j++) {
                float cv = cs[i][fl + j];
                float sv = ss[i][fl + j];
                float kr = lo ? ka[j] * cv - kp[j] * sv
                              : ka[j] * cv + kp[j] * sv;
                dot += qr[j] * kr;
            }
#pragma unroll
            for (int o = 16; o > 0; o >>= 1)
                dot += __shfl_xor_sync(0xffffffffu, dot, o);

            float score = dot * 0.08838834764831845f;  // 1/sqrt(128)
            float mn = fmaxf(mval, score);
            float corr = __expf(mval - mn);
            float w = __expf(score - mn);
            lsum = lsum * corr + w;
#pragma unroll
            for (int j = 0; j < 4; j++)
                acc[j] = acc[j] * corr + w * va[j];
            mval = mn;
        }
    }

    const int idx = (b * NSPLIT + s) * NHEAD + h;
    float* pa = g_part_acc + (long)idx * HDIM + lane * 4;
    pa[0] = acc[0]; pa[1] = acc[1]; pa[2] = acc[2]; pa[3] = acc[3];
    if (lane == 0) {
        g_part_m[idx] = mval;
        g_part_l[idx] = lsum;
    }
}

// ---------------------------------------------------------------------------
// Kernel B: combine the NSPLIT softmax partials.  grid = B*H, block = 128 (d)
// ---------------------------------------------------------------------------
__global__ __launch_bounds__(128) void attn_reduce_kernel()
{
    const int bh = blockIdx.x;
    const int b = bh >> 3;
    const int h = bh & 7;
    const int d = threadIdx.x;

    float M = -INFINITY;
#pragma unroll
    for (int s = 0; s < NSPLIT; s++)
        M = fmaxf(M, g_part_m[(b * NSPLIT + s) * NHEAD + h]);

    float num = 0.0f, den = 0.0f;
    for (int s = 0; s < NSPLIT; s++) {
        int idx = (b * NSPLIT + s) * NHEAD + h;
        float sc = __expf(g_part_m[idx] - M);
        num += g_part_acc[(long)idx * HDIM + d] * sc;
        den += g_part_l[idx] * sc;
    }
    g_attn[b * HID + h * HDIM + d] = num / den;
}

// ---------------------------------------------------------------------------
// Kernel C: split-K GEMM partials: out_part[kb][b][j] = sum_k a[b][k] W[k][j]
// grid = (8 colblocks, KSPLIT), block = 128 (one column each)
// ---------------------------------------------------------------------------
__global__ __launch_bounds__(128) void gemm_partial_kernel(const float* __restrict__ W)
{
    __shared__ float aS[BATCH][GEMM_KB];
    const int cb = blockIdx.x;
    const int kb = blockIdx.y;
    const int j = cb * 128 + threadIdx.x;
    const int k0 = kb * GEMM_KB;

    for (int e = threadIdx.x; e < BATCH * GEMM_KB; e += 128) {
        int bb = e / GEMM_KB;
        int kk = e % GEMM_KB;
        aS[bb][kk] = g_attn[bb * HID + k0 + kk];
    }
    __syncthreads();

    float accb[BATCH];
#pragma unroll
    for (int bb = 0; bb < BATCH; bb++) accb[bb] = 0.0f;

    for (int kk = 0; kk < GEMM_KB; kk++) {
        float w = W[(long)(k0 + kk) * HID + j];
#pragma unroll
        for (int bb = 0; bb < BATCH; bb++)
            accb[bb] = fmaf(aS[bb][kk], w, accb[bb]);
    }
#pragma unroll
    for (int bb = 0; bb < BATCH; bb++)
        g_gemm_part[(kb * BATCH + bb) * HID + j] = accb[bb];
}

// ---------------------------------------------------------------------------
// Kernel D: sum k-split partials into final output. grid = 64, block = 256
// ---------------------------------------------------------------------------
__global__ __launch_bounds__(256) void gemm_final_kernel(float* __restrict__ out)
{
    const int idx = blockIdx.x * 256 + threadIdx.x;  // over B*HID = 16384
    float sum = 0.0f;
#pragma unroll
    for (int kb = 0; kb < KSPLIT; kb++)
        sum += g_gemm_part[kb * BATCH * HID + idx];
    out[idx] = sum;
}

// ---------------------------------------------------------------------------
extern "C" void kernel_launch(void* const* d_in, const int* in_sizes, int n_in,
                              void* d_out, int out_size)
{
    const float* q  = (const float*)d_in[0];
    const float* k  = (const float*)d_in[1];
    const float* v  = (const float*)d_in[2];
    // d_in[3] = positions (unused; equals seq_lens - 1)
    const float* kc = (const float*)d_in[4];
    const float* vc = (const float*)d_in[5];
    const int* bt   = (const int*)d_in[6];
    const int* sl   = (const int*)d_in[7];
    const float* Wo = (const float*)d_in[8];
    float* out = (float*)d_out;

    attn_partial_kernel<<<dim3(NSPLIT, BATCH), 256>>>(q, k, v, kc, vc, bt, sl);
    attn_reduce_kernel<<<BATCH * NHEAD, 128>>>();
    gemm_partial_kernel<<<dim3(8, KSPLIT), 128>>>(Wo);
    gemm_final_kernel<<<64, 256>>>(out);
}